// round 11
// baseline (speedup 1.0000x reference)
#include <cuda_runtime.h>
#include <cuda_fp16.h>
#include <cstring>

// BilateralGrid apply, fp16 z-interleaved grid gather + half2 corner accumulation.
// grid (16,16,8,12) f32 is converted IN-CTA while staging to SMEM:
//   sg[yx][z][j] = half2( g[yx,z,j], g[yx,z+1,j] ),  z in [0,7)
// One 48B record gives both z-corners -> 4 random SMEM gathers/pixel (192 B/px,
// the information floor for fp16 trilerp). (y,x) bilinear reduction in half2
// (z0/z1 in lanes), fp32 z-combine + affine apply.
// Single resident wave: 296 CTAs = 2 per SM, 320 threads (20 warps/SM).

static constexpr int SH = 16;
static constexpr int SW = 16;
static constexpr int SL = 8;
static constexpr int ZI = SL - 1;                      // 7 interleaved z slots
static constexpr int CONV_ELEMS = SH * SW * ZI * 12;   // 21504 half2
static constexpr int CONV_BYTES = CONV_ELEMS * 4;      // 86016 B

static __device__ __forceinline__ void apply_one(
    float r, float g, float b, float cx, float cy,
    const __half2* __restrict__ sg,
    float& or_, float& og_, float& ob_)
{
    float guide = 0.2126f * r + 0.7152f * g + 0.0722f * b;

    float gx = fminf(fmaxf(cx * (SW - 1), 0.0f), SW - 1.001f);
    float gy = fminf(fmaxf(cy * (SH - 1), 0.0f), SH - 1.001f);
    float gcl = fminf(fmaxf(guide, 0.0f), 1.0f);
    float gz = fminf(fmaxf(gcl * (SL - 1), 0.0f), SL - 1.001f);

    int x0 = (int)gx;
    int y0 = (int)gy;
    int z0 = (int)gz;     // 0..6

    float fx = gx - (float)x0;
    float fy = gy - (float)y0;
    float fz = gz - (float)z0;
    float ex = 1.0f - fx, ey = 1.0f - fy, ez = 1.0f - fz;

    // (y,x) corner weights broadcast to both half2 lanes (z rides the lanes).
    __half2 hw00 = __float2half2_rn(ey * ex);
    __half2 hw01 = __float2half2_rn(ey * fx);
    __half2 hw10 = __float2half2_rn(fy * ex);
    __half2 hw11 = __float2half2_rn(fy * fx);

    int base = ((y0 * SW + x0) * ZI + z0) * 12;   // half2 units

    __half2 A0, A1, A2, A3, A4, A5, A6, A7, A8, A9, A10, A11;

#define CORNER_FIRST(OFF, HW)                                                  \
    {                                                                          \
        const uint4* cp = (const uint4*)(sg + base + (OFF));                   \
        uint4 qa = cp[0]; uint4 qb = cp[1]; uint4 qc = cp[2];                  \
        const __half2* h = (const __half2*)&qa;                                \
        A0 = __hmul2(HW, h[0]); A1 = __hmul2(HW, h[1]);                        \
        A2 = __hmul2(HW, h[2]); A3 = __hmul2(HW, h[3]);                        \
        h = (const __half2*)&qb;                                               \
        A4 = __hmul2(HW, h[0]); A5 = __hmul2(HW, h[1]);                        \
        A6 = __hmul2(HW, h[2]); A7 = __hmul2(HW, h[3]);                        \
        h = (const __half2*)&qc;                                               \
        A8 = __hmul2(HW, h[0]); A9 = __hmul2(HW, h[1]);                        \
        A10 = __hmul2(HW, h[2]); A11 = __hmul2(HW, h[3]);                      \
    }

#define CORNER(OFF, HW)                                                        \
    {                                                                          \
        const uint4* cp = (const uint4*)(sg + base + (OFF));                   \
        uint4 qa = cp[0]; uint4 qb = cp[1]; uint4 qc = cp[2];                  \
        const __half2* h = (const __half2*)&qa;                                \
        A0 = __hfma2(HW, h[0], A0); A1 = __hfma2(HW, h[1], A1);                \
        A2 = __hfma2(HW, h[2], A2); A3 = __hfma2(HW, h[3], A3);                \
        h = (const __half2*)&qb;                                               \
        A4 = __hfma2(HW, h[0], A4); A5 = __hfma2(HW, h[1], A5);                \
        A6 = __hfma2(HW, h[2], A6); A7 = __hfma2(HW, h[3], A7);                \
        h = (const __half2*)&qc;                                               \
        A8 = __hfma2(HW, h[0], A8); A9 = __hfma2(HW, h[1], A9);                \
        A10 = __hfma2(HW, h[2], A10); A11 = __hfma2(HW, h[3], A11);            \
    }

    CORNER_FIRST(0,                        hw00);   // (y0, x0)
    CORNER      (ZI * 12,                  hw01);   // (y0, x1)
    CORNER      (SW * ZI * 12,             hw10);   // (y1, x0)
    CORNER      (SW * ZI * 12 + ZI * 12,   hw11);   // (y1, x1)
#undef CORNER
#undef CORNER_FIRST

    // fp32 z-combine: a_j = lo*ez + hi*fz
#define ZC(AH) ({ float2 f_ = __half22float2(AH); f_.x * ez + f_.y * fz; })
    float a0 = ZC(A0), a1 = ZC(A1), a2 = ZC(A2), a3 = ZC(A3);
    float a4 = ZC(A4), a5 = ZC(A5), a6 = ZC(A6), a7 = ZC(A7);
    float a8 = ZC(A8), a9 = ZC(A9), a10 = ZC(A10), a11 = ZC(A11);
#undef ZC

    or_ = a0 * r + a1 * g + a2 * b + a3;
    og_ = a4 * r + a5 * g + a6 * b + a7;
    ob_ = a8 * r + a9 * g + a10 * b + a11;
}

__global__ void __launch_bounds__(320, 2)
bilateral_grid_kernel(const float4* __restrict__ px,   // 3 float4 per quad
                      const float4* __restrict__ cd,   // 2 float4 per quad
                      const float* __restrict__ grid,  // f32 (16,16,8,12)
                      float4* __restrict__ out,        // 3 float4 per quad
                      int nquads)
{
    extern __shared__ __half2 sg[];

    // Fused convert+stage: each thread builds 4 consecutive half2 per iter.
    // half2 index g = i*4: j = g%12 in {0,4,8}; t = g/12; z = t%7; yx = t/7.
    // src lo = grid[(yx*8+z)*12 + j .. +3], hi = src + 12 (z+1 record).
    for (int i = threadIdx.x; i < CONV_ELEMS / 4; i += blockDim.x) {
        int gidx = i * 4;
        int j = gidx % 12;
        int t = gidx / 12;
        int z = t % ZI;
        int yx = t / ZI;
        const float4* lo4 = (const float4*)(grid + (yx * SL + z) * 12 + j);
        const float4* hi4 = (const float4*)(grid + (yx * SL + z + 1) * 12 + j);
        float4 lo = __ldg(lo4);
        float4 hi = __ldg(hi4);
        __align__(16) __half2 pack[4];
        pack[0] = __floats2half2_rn(lo.x, hi.x);
        pack[1] = __floats2half2_rn(lo.y, hi.y);
        pack[2] = __floats2half2_rn(lo.z, hi.z);
        pack[3] = __floats2half2_rn(lo.w, hi.w);
        uint4 bits;
        memcpy(&bits, pack, sizeof(uint4));
        ((uint4*)sg)[i] = bits;
    }
    __syncthreads();

    int stride = gridDim.x * blockDim.x;

    for (int q = blockIdx.x * blockDim.x + threadIdx.x; q < nquads; q += stride) {
        float4 p0 = px[q * 3 + 0];
        float4 p1 = px[q * 3 + 1];
        float4 p2 = px[q * 3 + 2];
        float4 c0 = cd[q * 2 + 0];
        float4 c1 = cd[q * 2 + 1];

        float4 o0, o1, o2;

        apply_one(p0.x, p0.y, p0.z, c0.x, c0.y, sg, o0.x, o0.y, o0.z);
        apply_one(p0.w, p1.x, p1.y, c0.z, c0.w, sg, o0.w, o1.x, o1.y);
        apply_one(p1.z, p1.w, p2.x, c1.x, c1.y, sg, o1.z, o1.w, o2.x);
        apply_one(p2.y, p2.z, p2.w, c1.z, c1.w, sg, o2.y, o2.z, o2.w);

        out[q * 3 + 0] = o0;
        out[q * 3 + 1] = o1;
        out[q * 3 + 2] = o2;
    }
}

extern "C" void kernel_launch(void* const* d_in, const int* in_sizes, int n_in,
                              void* d_out, int out_size)
{
    const float* pixels = (const float*)d_in[0];  // N*3
    const float* coords = (const float*)d_in[1];  // N*2
    const float* grid   = (const float*)d_in[2];  // 16*16*8*12

    int n_pixels = in_sizes[0] / 3;
    int nquads = n_pixels / 4;     // 2,073,600

    cudaFuncSetAttribute(bilateral_grid_kernel,
                         cudaFuncAttributeMaxDynamicSharedMemorySize, CONV_BYTES);

    // Single resident wave: 2 CTAs/SM * 148 SMs, grid-stride inside.
    bilateral_grid_kernel<<<296, 320, CONV_BYTES>>>(
        (const float4*)pixels, (const float4*)coords, grid,
        (float4*)d_out, nquads);
}